// round 12
// baseline (speedup 1.0000x reference)
#include <cuda_runtime.h>
#include <math.h>
#include <stdint.h>

#define Nn 4096
#define Mm 4096
#define LAMDA 0.01f
#define STOP_THR 1e-7
#define MAX_ITER 100
#define NB 128
#define NT 512
#define NW 16
#define S2 70   // smem row stride (floats), even (8B smem accesses)

typedef unsigned long long ull;

// ---------------- device globals ----------------
__device__ float    g_K[(size_t)Nn * Mm];            // 64 MB fp32 K
__device__ unsigned g_Kh[(size_t)Nn * (Mm / 2)];     // 32 MB bf16 K   (row-major)
__device__ unsigned g_KTh[(size_t)Mm * (Nn / 2)];    // 32 MB bf16 K^T (row-major)
__device__ float  g_a[2][Nn];
__device__ float  g_b[2][Mm];
__device__ double g_bdisp[NB];
__device__ double g_bcost[NB];
__device__ int    g_final;
__device__ unsigned g_bar_cnt;     // monotonic
__device__ unsigned g_epi_ticket;  // monotonic

// ---------------- fast exp: FFMA-only ----------------
__device__ __forceinline__ float fexp(float xx) {
    float t  = fmaf(xx, 1.4426950408889634f, 12582912.0f);
    int   n  = __float_as_int(t) - 0x4B400000;
    float fn = t - 12582912.0f;
    float r  = fmaf(fn, -0.693145751953125f, xx);
    r        = fmaf(fn, -1.42860677e-6f, r);
    float p  = 1.3888890e-3f;
    p = fmaf(p, r, 8.3333338e-3f);
    p = fmaf(p, r, 4.1666668e-2f);
    p = fmaf(p, r, 1.6666667e-1f);
    p = fmaf(p, r, 5.0000000e-1f);
    p = fmaf(p, r, 1.0f);
    p = fmaf(p, r, 1.0f);
    return __int_as_float(__float_as_int(p) + (n << 23));
}

#define FMA2(d, a, b) \
    asm("fma.rn.f32x2 %0, %1, %2, %0;" : "+l"(d) : "l"(a), "l"(b))
#define MUL2(d, a, b) \
    asm("mul.rn.f32x2 %0, %1, %2;" : "=l"(d) : "l"(a), "l"(b))
#define UNPACK2(lo, hi, v) \
    asm("mov.b64 {%0, %1}, %2;" : "=f"(lo), "=f"(hi) : "l"(v))
#define PACKF2(d, lo, hi) \
    asm("mov.b64 %0, {%1, %2};" : "=l"(d) : "f"(lo), "f"(hi))
#define CVT_BF16X2(r, hi, lo) \
    asm("cvt.rn.satfinite.bf16x2.f32 %0, %1, %2;" : "=r"(r) : "f"(hi), "f"(lo))

__device__ __forceinline__ ull bf2_to_f32x2(unsigned v) {
    float lo = __uint_as_float(v << 16);
    float hi = __uint_as_float(v & 0xffff0000u);
    ull d; PACKF2(d, lo, hi);
    return d;
}

// ------------- cheap acquire/release grid barrier -------
__device__ __forceinline__ void red_rel_add1(unsigned* p) {
    asm volatile("red.release.gpu.global.add.u32 [%0], 1;" :: "l"(p) : "memory");
}
__device__ __forceinline__ unsigned ld_acq(unsigned* p) {
    unsigned v;
    asm volatile("ld.acquire.gpu.global.u32 %0, [%1];" : "=r"(v) : "l"(p) : "memory");
    return v;
}
__device__ __forceinline__ void gbar(unsigned target) {
    __syncthreads();
    if (threadIdx.x == 0) {
        red_rel_add1(&g_bar_cnt);
        while ((int)(ld_acq(&g_bar_cnt) - target) < 0) { }
    }
    __syncthreads();
}

// ===================== Kernel 1: CK build (proven) =====================
__global__ void __launch_bounds__(NT, 1)
ck_kernel(const float* __restrict__ x, const float* __restrict__ y) {
    extern __shared__ float sm[];
    float* XS = sm;                 // [128][S2]
    float* YS = sm + 128 * S2;      // [128][S2]
    float* xn = YS + 128 * S2;      // [128]
    float* yn = xn + 128;           // [128]

    const int tid = threadIdx.x, blk = blockIdx.x;
    const int lane = tid & 31, warp = tid >> 5;

    if (tid < 32) {
        g_a[0][blk * 32 + tid] = 1.0f / (float)Nn;
        g_b[0][blk * 32 + tid] = 1.0f;
    }

    const int i0 = (blk >> 2) * 128;
    for (int t = tid; t < 4096; t += NT) {
        int r = t >> 5, c = t & 31;
        float2 v = __ldg((const float2*)(x + (size_t)(i0 + r) * 64) + c);
        *(float2*)(XS + r * S2 + 2 * c) = v;
    }
    __syncthreads();
    if (tid < 128) {
        float s = 0.f;
        #pragma unroll
        for (int k = 0; k < 64; k++) { float v = XS[tid * S2 + k]; s = fmaf(v, v, s); }
        xn[tid] = s;
    }

    const int iy = warp * 8;
    for (int s = 0; s < 8; s++) {
        const int j0 = ((blk & 3) * 8 + s) * 128;
        __syncthreads();
        for (int t = tid; t < 4096; t += NT) {
            int r = t >> 5, c = t & 31;
            float2 v = __ldg((const float2*)(y + (size_t)(j0 + r) * 64) + c);
            *(float2*)(YS + r * S2 + 2 * c) = v;
        }
        __syncthreads();
        if (tid < 128) {
            float sv = 0.f;
            #pragma unroll
            for (int k = 0; k < 64; k++) { float v = YS[tid * S2 + k]; sv = fmaf(v, v, sv); }
            yn[tid] = sv;
        }
        __syncthreads();

        ull acc[8][4];
        #pragma unroll
        for (int u = 0; u < 8; u++)
            #pragma unroll
            for (int w = 0; w < 4; w++) acc[u][w] = 0ULL;

        #pragma unroll 2
        for (int kp = 0; kp < 32; kp++) {
            const int k = kp * 2;
            ull xp[8], yp[4];
            #pragma unroll
            for (int u = 0; u < 8; u++)
                xp[u] = *(const ull*)(XS + (iy + u) * S2 + k);
            #pragma unroll
            for (int w = 0; w < 4; w++)
                yp[w] = *(const ull*)(YS + (lane + 32 * w) * S2 + k);
            #pragma unroll
            for (int u = 0; u < 8; u++)
                #pragma unroll
                for (int w = 0; w < 4; w++)
                    FMA2(acc[u][w], xp[u], yp[w]);
        }

        #pragma unroll
        for (int u = 0; u < 8; u++) {
            const int i = i0 + iy + u;
            const float xni = xn[iy + u];
            #pragma unroll
            for (int w = 0; w < 4; w++) {
                const int jl = lane + 32 * w;
                float lo, hi;
                UNPACK2(lo, hi, acc[u][w]);
                float Cv = xni + yn[jl] - 2.0f * (lo + hi);
                g_K[(size_t)i * Mm + j0 + jl] = fexp(-LAMDA * Cv);
            }
        }
    }
}

// ===================== Kernel 2: repack K -> bf16 Kh + transposed KTh ===
// 1024 tiles of 128x128; 8 per block.
__global__ void __launch_bounds__(NT, 1)
repack_kernel() {
    __shared__ unsigned U[128][65];    // bf16x2 per (row, col-pair)

    const int tid = threadIdx.x, blk = blockIdx.x;
    for (int t8 = 0; t8 < 8; t8++) {
        const int tile = blk * 8 + t8;
        const int i0 = (tile >> 5) * 128, j0 = (tile & 31) * 128;

        __syncthreads();   // previous tile's U fully consumed
        // phase 1: read fp32 K rows, emit Kh + smem U
        for (int idx = tid; idx < 128 * 64; idx += NT) {
            const int r = idx >> 6, q = idx & 63;
            float2 v = *(const float2*)(g_K + (size_t)(i0 + r) * Mm + j0 + 2 * q);
            unsigned u; CVT_BF16X2(u, v.y, v.x);
            g_Kh[(size_t)(i0 + r) * (Mm / 2) + (j0 >> 1) + q] = u;
            U[r][q] = u;
        }
        __syncthreads();
        // phase 2: emit KTh rows (j = tile column), coalesced by p
        for (int idx = tid; idx < 128 * 64; idx += NT) {
            const int j = idx >> 6, p = idx & 63;
            const int jq = j >> 1;
            unsigned u0 = U[2 * p][jq], u1 = U[2 * p + 1][jq];
            unsigned o = __byte_perm(u0, u1, (j & 1) ? 0x7632 : 0x5410);
            g_KTh[(size_t)(j0 + j) * (Nn / 2) + (i0 >> 1) + p] = o;
        }
    }
}

// ===================== Kernel 3: Sinkhorn loop (bf16) =====================
__global__ void __launch_bounds__(NT, 1)
sink_kernel(const float* __restrict__ mu, const float* __restrict__ nu) {
    __shared__ float  sA[Nn];
    __shared__ float  sB[Mm];
    __shared__ double sRow[32];
    __shared__ double sDS1[32];
    __shared__ double sDisp;

    const int tid = threadIdx.x, blk = blockIdx.x;
    const int warp = tid >> 5, lane = tid & 31;
    const unsigned FULL = 0xffffffffu;
    const unsigned base = __ldcg(&g_bar_cnt);
    unsigned gen = 0;
    int fpar = 0;

    for (int it = 0; it < MAX_ITER; ++it) {
        const int cur = it & 1, nxt = cur ^ 1;

        // ---- deferred convergence check on it-1
        if (it > 0) {
            if (warp == 0) {
                double sd = __ldcg(&g_bdisp[lane])      + __ldcg(&g_bdisp[lane + 32])
                          + __ldcg(&g_bdisp[lane + 64]) + __ldcg(&g_bdisp[lane + 96]);
                #pragma unroll
                for (int off = 16; off; off >>= 1)
                    sd += __shfl_down_sync(FULL, sd, off);
                if (lane == 0) sDisp = sd;
            }
            __syncthreads();
            if (sDisp <= STOP_THR) { fpar = cur; break; }
            __syncthreads();
        }

        // ---- Phase A: b[nxt] = nu / (K^T a[cur]), via KTh rows (2/warp)
        for (int i = tid; i < Nn; i += NT) sA[i] = __ldcg(&g_a[cur][i]);
        __syncthreads();
        {
            const int j0r = blk * 32 + warp * 2;
            const uint2* Ka = (const uint2*)(g_KTh + (size_t)j0r * (Nn / 2));
            const uint2* Kb = (const uint2*)(g_KTh + (size_t)(j0r + 1) * (Nn / 2));
            const ull* A2 = (const ull*)sA;
            ull ta = 0ULL, tb = 0ULL;
            #pragma unroll 4
            for (int q = lane; q < Nn / 4; q += 32) {
                uint2 va = Ka[q], vb = Kb[q];
                ull a0 = A2[2 * q], a1 = A2[2 * q + 1];
                FMA2(ta, bf2_to_f32x2(va.x), a0);
                FMA2(ta, bf2_to_f32x2(va.y), a1);
                FMA2(tb, bf2_to_f32x2(vb.x), a0);
                FMA2(tb, bf2_to_f32x2(vb.y), a1);
            }
            float l, h;
            UNPACK2(l, h, ta); float tfa = l + h;
            UNPACK2(l, h, tb); float tfb = l + h;
            #pragma unroll
            for (int off = 16; off; off >>= 1) {
                tfa += __shfl_down_sync(FULL, tfa, off);
                tfb += __shfl_down_sync(FULL, tfb, off);
            }
            if (lane == 0) {
                g_b[nxt][j0r]     = __ldg(&nu[j0r])     / tfa;
                g_b[nxt][j0r + 1] = __ldg(&nu[j0r + 1]) / tfb;
            }
        }
        gbar(base + (++gen) * NB);

        // ---- Phase B: a[nxt] = mu/(K b_new) + fused disp (2 rows interleaved)
        for (int i = tid; i < Mm; i += NT) sA[i] = __ldcg(&g_b[nxt][i]);
        for (int i = tid; i < Mm; i += NT) sB[i] = __ldcg(&g_b[cur][i]);
        __syncthreads();
        {
            const int i0r = blk * 32 + warp * 2;
            const uint2* Ka = (const uint2*)(g_Kh + (size_t)i0r * (Mm / 2));
            const uint2* Kb = (const uint2*)(g_Kh + (size_t)(i0r + 1) * (Mm / 2));
            const ull* A2 = (const ull*)sA;
            const ull* B2 = (const ull*)sB;
            ull ta = 0ULL, s1a = 0ULL, s2a = 0ULL;
            ull tb = 0ULL, s1b = 0ULL, s2b = 0ULL;
            #pragma unroll 4
            for (int q = lane; q < Mm / 4; q += 32) {
                uint2 va = Ka[q], vb = Kb[q];
                ull bn0 = A2[2 * q], bn1 = A2[2 * q + 1];
                ull be0 = B2[2 * q], be1 = B2[2 * q + 1];
                ull k, k2, tmp;
                k = bf2_to_f32x2(va.x);
                MUL2(k2, k, k);
                FMA2(ta, k, bn0);
                MUL2(tmp, k2, bn0);
                FMA2(s1a, tmp, bn0);
                FMA2(s2a, tmp, be0);
                k = bf2_to_f32x2(va.y);
                MUL2(k2, k, k);
                FMA2(ta, k, bn1);
                MUL2(tmp, k2, bn1);
                FMA2(s1a, tmp, bn1);
                FMA2(s2a, tmp, be1);
                k = bf2_to_f32x2(vb.x);
                MUL2(k2, k, k);
                FMA2(tb, k, bn0);
                MUL2(tmp, k2, bn0);
                FMA2(s1b, tmp, bn0);
                FMA2(s2b, tmp, be0);
                k = bf2_to_f32x2(vb.y);
                MUL2(k2, k, k);
                FMA2(tb, k, bn1);
                MUL2(tmp, k2, bn1);
                FMA2(s1b, tmp, bn1);
                FMA2(s2b, tmp, be1);
            }
            float l, h;
            UNPACK2(l, h, ta);  float tfa = l + h;
            UNPACK2(l, h, s1a); float s1fa = l + h;
            UNPACK2(l, h, s2a); float s2fa = l + h;
            UNPACK2(l, h, tb);  float tfb = l + h;
            UNPACK2(l, h, s1b); float s1fb = l + h;
            UNPACK2(l, h, s2b); float s2fb = l + h;
            #pragma unroll
            for (int off = 16; off; off >>= 1) {
                tfa  += __shfl_down_sync(FULL, tfa,  off);
                s1fa += __shfl_down_sync(FULL, s1fa, off);
                s2fa += __shfl_down_sync(FULL, s2fa, off);
                tfb  += __shfl_down_sync(FULL, tfb,  off);
                s1fb += __shfl_down_sync(FULL, s1fb, off);
                s2fb += __shfl_down_sync(FULL, s2fb, off);
            }
            if (lane == 0) {
                {
                    const int i = i0r;
                    float an = __ldg(&mu[i]) / tfa;
                    g_a[nxt][i] = an;
                    double dan = (double)an;
                    double dao = (double)__ldcg(&g_a[cur][i]);
                    double dS1 = dan * dan * (double)s1fa;
                    double d = (it == 0)
                        ? dS1
                        : dS1 - 2.0 * dan * dao * (double)s2fa + sDS1[warp * 2];
                    sDS1[warp * 2] = dS1;
                    sRow[warp * 2] = d;
                }
                {
                    const int i = i0r + 1;
                    float an = __ldg(&mu[i]) / tfb;
                    g_a[nxt][i] = an;
                    double dan = (double)an;
                    double dao = (double)__ldcg(&g_a[cur][i]);
                    double dS1 = dan * dan * (double)s1fb;
                    double d = (it == 0)
                        ? dS1
                        : dS1 - 2.0 * dan * dao * (double)s2fb + sDS1[warp * 2 + 1];
                    sDS1[warp * 2 + 1] = dS1;
                    sRow[warp * 2 + 1] = d;
                }
            }
        }
        __syncthreads();
        if (tid == 0) {
            double s = 0.0;
            #pragma unroll
            for (int q = 0; q < 32; ++q) s += sRow[q];
            g_bdisp[blk] = s;
        }
        fpar = nxt;
        gbar(base + (++gen) * NB);
    }

    if (blk == 0 && tid == 0) g_final = fpar;
}

// ===================== Kernel 4: epilogue + last-block cost reduce =======
__global__ void __launch_bounds__(NT, 1)
epi_kernel(float* __restrict__ out) {
    __shared__ float  sA[Mm];
    __shared__ float  sB[Mm];
    __shared__ double sRow[32];
    __shared__ int    sLast;

    const int tid = threadIdx.x, blk = blockIdx.x;
    const int warp = tid >> 5, lane = tid & 31;
    const unsigned FULL = 0xffffffffu;
    const int fpar = __ldcg(&g_final);

    float* Pout = out + 1;
    float* Cmat = out + 1 + (size_t)Nn * Mm;

    for (int i = tid; i < Mm; i += NT) sA[i] = __ldcg(&g_b[fpar][i]);
    __syncthreads();
    for (int m = tid; m < Mm - 3; m += NT) sB[m] = sA[m + 3];
    __syncthreads();
    const float4* Bsh4 = (const float4*)sB;

    #pragma unroll
    for (int rr = 0; rr < 2; ++rr) {
        const int i = blk * 32 + warp * 2 + rr;
        const float ai = __ldcg(&g_a[fpar][i]);
        const float*  Kr = g_K + (size_t)i * Mm;
        const float4* K4 = (const float4*)Kr;
        float* Pr = Pout + (size_t)i * Mm;
        float* Cr = Cmat + (size_t)i * Mm;
        float csum = 0.f;

        if (lane < 3) {                  // head j = 0,1,2
            float k = Kr[lane];
            float p = ai * k * sA[lane];
            float c = -69.31471805599453f * __log2f(k);
            __stcs(Pr + lane, p);
            __stcs(Cr + lane, c);
            csum = fmaf(p, c, csum);
        }

        float4 curr = K4[lane];
        for (int s = 0; s < 32; s++) {
            const int q = lane + 32 * s;
            const int nidx = (s < 31) ? (lane + 32 * (s + 1)) : lane;
            float4 newq = K4[nidx];
            float nx = __shfl_down_sync(FULL, curr.x, 1);
            float ny = __shfl_down_sync(FULL, curr.y, 1);
            float nz = __shfl_down_sync(FULL, curr.z, 1);
            float bx = __shfl_sync(FULL, newq.x, 0);
            float by = __shfl_sync(FULL, newq.y, 0);
            float bz = __shfl_sync(FULL, newq.z, 0);
            if (lane == 31) { nx = bx; ny = by; nz = bz; }

            if (q <= 1022) {
                const int jst = 4 * q + 3;
                float k0 = curr.w, k1 = nx, k2 = ny, k3 = nz;
                float4 bq = Bsh4[q];
                float p0 = ai * k0 * bq.x, p1 = ai * k1 * bq.y;
                float p2 = ai * k2 * bq.z, p3 = ai * k3 * bq.w;
                float c0 = -69.31471805599453f * __log2f(k0);
                float c1 = -69.31471805599453f * __log2f(k1);
                float c2 = -69.31471805599453f * __log2f(k2);
                float c3 = -69.31471805599453f * __log2f(k3);
                float4 pq; pq.x = p0; pq.y = p1; pq.z = p2; pq.w = p3;
                float4 cq; cq.x = c0; cq.y = c1; cq.z = c2; cq.w = c3;
                __stcs((float4*)(Pr + jst), pq);
                __stcs((float4*)(Cr + jst), cq);
                csum = fmaf(p0, c0, csum); csum = fmaf(p1, c1, csum);
                csum = fmaf(p2, c2, csum); csum = fmaf(p3, c3, csum);
            }
            if (s == 31 && lane == 31) {  // tail j = 4095
                float k = curr.w;
                float p = ai * k * sA[4095];
                float c = -69.31471805599453f * __log2f(k);
                __stcs(Pr + 4095, p);
                __stcs(Cr + 4095, c);
                csum = fmaf(p, c, csum);
            }
            curr = newq;
        }

        #pragma unroll
        for (int off = 16; off; off >>= 1)
            csum += __shfl_down_sync(FULL, csum, off);
        if (lane == 0) sRow[warp * 2 + rr] = (double)csum;
    }
    __syncthreads();
    if (tid == 0) {
        double s = 0.0;
        #pragma unroll
        for (int q = 0; q < 32; ++q) s += sRow[q];
        g_bcost[blk] = s;
        __threadfence();
        unsigned old;
        asm volatile("atom.global.add.u32 %0, [%1], 1;"
                     : "=r"(old) : "l"(&g_epi_ticket) : "memory");
        sLast = ((old + 1) % NB == 0);
    }
    __syncthreads();
    if (sLast) {                       // last block: final cost reduce
        __threadfence();
        if (warp == 0) {
            double sc = __ldcg(&g_bcost[lane])      + __ldcg(&g_bcost[lane + 32])
                      + __ldcg(&g_bcost[lane + 64]) + __ldcg(&g_bcost[lane + 96]);
            #pragma unroll
            for (int off = 16; off; off >>= 1)
                sc += __shfl_down_sync(FULL, sc, off);
            if (lane == 0) out[0] = (float)sc;
        }
    }
}

// ---------------- launch ----------------
extern "C" void kernel_launch(void* const* d_in, const int* in_sizes, int n_in,
                              void* d_out, int out_size) {
    const float* x  = (const float*)d_in[0];
    const float* y  = (const float*)d_in[1];
    const float* mu = (const float*)d_in[2];
    const float* nu = (const float*)d_in[3];
    float* out = (float*)d_out;

    const int ck_smem = (256 * S2 + 256) * (int)sizeof(float);
    cudaFuncSetAttribute(ck_kernel, cudaFuncAttributeMaxDynamicSharedMemorySize, ck_smem);

    ck_kernel<<<NB, NT, ck_smem>>>(x, y);
    repack_kernel<<<NB, NT>>>();
    sink_kernel<<<NB, NT>>>(mu, nu);
    epi_kernel<<<NB, NT>>>(out);
}

// round 13
// speedup vs baseline: 1.7717x; 1.7717x over previous
#include <cuda_runtime.h>
#include <math.h>
#include <stdint.h>

#define Nn 4096
#define Mm 4096
#define LAMDA 0.01f
#define STOP_THR 1e-7
#define MAX_ITER 100
#define NB 128
#define NT 512     // CK threads
#define NTS 1024   // sink/epi threads
#define NWS 32     // sink/epi warps
#define S2 70      // smem row stride (floats), even (8B smem accesses)

typedef unsigned long long ull;

// ---------------- device globals ----------------
__device__ float  g_K[(size_t)Nn * Mm];   // 64 MB fp32 K (L2-resident)
__device__ float  g_a[2][Nn];
__device__ float  g_b[2][Mm];
__device__ double g_bdisp[NB];
__device__ double g_bcost[NB];
__device__ int    g_final;
__device__ unsigned g_bar_cnt;     // monotonic
__device__ unsigned g_epi_ticket;  // monotonic

// ---------------- fast exp: FFMA-only ----------------
__device__ __forceinline__ float fexp(float xx) {
    float t  = fmaf(xx, 1.4426950408889634f, 12582912.0f);
    int   n  = __float_as_int(t) - 0x4B400000;
    float fn = t - 12582912.0f;
    float r  = fmaf(fn, -0.693145751953125f, xx);
    r        = fmaf(fn, -1.42860677e-6f, r);
    float p  = 1.3888890e-3f;
    p = fmaf(p, r, 8.3333338e-3f);
    p = fmaf(p, r, 4.1666668e-2f);
    p = fmaf(p, r, 1.6666667e-1f);
    p = fmaf(p, r, 5.0000000e-1f);
    p = fmaf(p, r, 1.0f);
    p = fmaf(p, r, 1.0f);
    return __int_as_float(__float_as_int(p) + (n << 23));
}

#define FMA2(d, a, b) \
    asm("fma.rn.f32x2 %0, %1, %2, %0;" : "+l"(d) : "l"(a), "l"(b))
#define MUL2(d, a, b) \
    asm("mul.rn.f32x2 %0, %1, %2;" : "=l"(d) : "l"(a), "l"(b))
#define UNPACK2(lo, hi, v) \
    asm("mov.b64 {%0, %1}, %2;" : "=f"(lo), "=f"(hi) : "l"(v))

// ------------- cheap acquire/release grid barrier -------
__device__ __forceinline__ void red_rel_add1(unsigned* p) {
    asm volatile("red.release.gpu.global.add.u32 [%0], 1;" :: "l"(p) : "memory");
}
__device__ __forceinline__ unsigned ld_acq(unsigned* p) {
    unsigned v;
    asm volatile("ld.acquire.gpu.global.u32 %0, [%1];" : "=r"(v) : "l"(p) : "memory");
    return v;
}
__device__ __forceinline__ void gbar(unsigned target) {
    __syncthreads();
    if (threadIdx.x == 0) {
        red_rel_add1(&g_bar_cnt);
        while ((int)(ld_acq(&g_bar_cnt) - target) < 0) { }
    }
    __syncthreads();
}

// ===================== Kernel 1: CK build (proven, NT=512) ================
__global__ void __launch_bounds__(NT, 1)
ck_kernel(const float* __restrict__ x, const float* __restrict__ y) {
    extern __shared__ float sm[];
    float* XS = sm;                 // [128][S2]
    float* YS = sm + 128 * S2;      // [128][S2]
    float* xn = YS + 128 * S2;      // [128]
    float* yn = xn + 128;           // [128]

    const int tid = threadIdx.x, blk = blockIdx.x;
    const int lane = tid & 31, warp = tid >> 5;

    if (tid < 32) {
        g_a[0][blk * 32 + tid] = 1.0f / (float)Nn;
        g_b[0][blk * 32 + tid] = 1.0f;
    }

    const int i0 = (blk >> 2) * 128;
    for (int t = tid; t < 4096; t += NT) {
        int r = t >> 5, c = t & 31;
        float2 v = __ldg((const float2*)(x + (size_t)(i0 + r) * 64) + c);
        *(float2*)(XS + r * S2 + 2 * c) = v;
    }
    __syncthreads();
    if (tid < 128) {
        float s = 0.f;
        #pragma unroll
        for (int k = 0; k < 64; k++) { float v = XS[tid * S2 + k]; s = fmaf(v, v, s); }
        xn[tid] = s;
    }

    const int iy = warp * 8;
    for (int s = 0; s < 8; s++) {
        const int j0 = ((blk & 3) * 8 + s) * 128;
        __syncthreads();
        for (int t = tid; t < 4096; t += NT) {
            int r = t >> 5, c = t & 31;
            float2 v = __ldg((const float2*)(y + (size_t)(j0 + r) * 64) + c);
            *(float2*)(YS + r * S2 + 2 * c) = v;
        }
        __syncthreads();
        if (tid < 128) {
            float sv = 0.f;
            #pragma unroll
            for (int k = 0; k < 64; k++) { float v = YS[tid * S2 + k]; sv = fmaf(v, v, sv); }
            yn[tid] = sv;
        }
        __syncthreads();

        ull acc[8][4];
        #pragma unroll
        for (int u = 0; u < 8; u++)
            #pragma unroll
            for (int w = 0; w < 4; w++) acc[u][w] = 0ULL;

        #pragma unroll 2
        for (int kp = 0; kp < 32; kp++) {
            const int k = kp * 2;
            ull xp[8], yp[4];
            #pragma unroll
            for (int u = 0; u < 8; u++)
                xp[u] = *(const ull*)(XS + (iy + u) * S2 + k);
            #pragma unroll
            for (int w = 0; w < 4; w++)
                yp[w] = *(const ull*)(YS + (lane + 32 * w) * S2 + k);
            #pragma unroll
            for (int u = 0; u < 8; u++)
                #pragma unroll
                for (int w = 0; w < 4; w++)
                    FMA2(acc[u][w], xp[u], yp[w]);
        }

        #pragma unroll
        for (int u = 0; u < 8; u++) {
            const int i = i0 + iy + u;
            const float xni = xn[iy + u];
            #pragma unroll
            for (int w = 0; w < 4; w++) {
                const int jl = lane + 32 * w;
                float lo, hi;
                UNPACK2(lo, hi, acc[u][w]);
                float Cv = xni + yn[jl] - 2.0f * (lo + hi);
                g_K[(size_t)i * Mm + j0 + jl] = fexp(-LAMDA * Cv);
            }
        }
    }
}

// ===================== Kernel 2: Sinkhorn loop (NT=1024) ===================
__global__ void __launch_bounds__(NTS, 1)
sink_kernel(const float* __restrict__ mu, const float* __restrict__ nu) {
    __shared__ float  sA[Nn];
    __shared__ float  sB[Mm];
    __shared__ float  sred[NWS][33];
    __shared__ double sRow[NWS];
    __shared__ double sDS1[NWS];
    __shared__ double sDisp;

    const int tid = threadIdx.x, blk = blockIdx.x;
    const int warp = tid >> 5, lane = tid & 31;
    const unsigned FULL = 0xffffffffu;
    const unsigned base = __ldcg(&g_bar_cnt);
    unsigned gen = 0;
    int fpar = 0;

    for (int it = 0; it < MAX_ITER; ++it) {
        const int cur = it & 1, nxt = cur ^ 1;

        // ---- deferred convergence check on it-1
        if (it > 0) {
            if (warp == 0) {
                double sd = __ldcg(&g_bdisp[lane])      + __ldcg(&g_bdisp[lane + 32])
                          + __ldcg(&g_bdisp[lane + 64]) + __ldcg(&g_bdisp[lane + 96]);
                #pragma unroll
                for (int off = 16; off; off >>= 1)
                    sd += __shfl_down_sync(FULL, sd, off);
                if (lane == 0) sDisp = sd;
            }
            __syncthreads();
            if (sDisp <= STOP_THR) { fpar = cur; break; }
            __syncthreads();
        }

        // ---- Phase A: b[nxt] = nu / (K^T a[cur]); block owns cols [blk*32,+32)
        for (int i = tid; i < Nn; i += NTS) sA[i] = __ldcg(&g_a[cur][i]);
        __syncthreads();
        {
            const int j = blk * 32 + lane;
            const float* Kc = g_K + j;
            float acc[8];
            #pragma unroll
            for (int u = 0; u < 8; u++) acc[u] = 0.f;
            for (int ib = 0; ib < Nn; ib += 256) {
                #pragma unroll
                for (int u = 0; u < 8; u++) {
                    const int i = ib + warp + 32 * u;
                    acc[u] = fmaf(Kc[(size_t)i * Mm], sA[i], acc[u]);
                }
            }
            float s = ((acc[0] + acc[1]) + (acc[2] + acc[3]))
                    + ((acc[4] + acc[5]) + (acc[6] + acc[7]));
            sred[warp][lane] = s;
        }
        __syncthreads();
        if (warp == 0) {
            float s = 0.f;
            #pragma unroll
            for (int w = 0; w < NWS; ++w) s += sred[w][lane];
            int j = blk * 32 + lane;
            g_b[nxt][j] = __ldg(&nu[j]) / s;
        }
        gbar(base + (++gen) * NB);

        // ---- Phase B: a[nxt] = mu/(K b_new) + fused disp (1 row per warp)
        for (int i = tid; i < Mm; i += NTS) sA[i] = __ldcg(&g_b[nxt][i]);
        for (int i = tid; i < Mm; i += NTS) sB[i] = __ldcg(&g_b[cur][i]);
        __syncthreads();
        {
            const int i = blk * 32 + warp;
            const ull* K2 = (const ull*)(g_K + (size_t)i * Mm);
            const ull* A2 = (const ull*)sA;
            const ull* B2 = (const ull*)sB;
            ull t = 0ULL, s1 = 0ULL, s2 = 0ULL;
            #pragma unroll 4
            for (int j = lane; j < Mm / 2; j += 32) {
                ull k = K2[j], bn = A2[j], be = B2[j];
                ull k2, tmp;
                MUL2(k2, k, k);
                FMA2(t, k, bn);
                MUL2(tmp, k2, bn);
                FMA2(s1, tmp, bn);
                FMA2(s2, tmp, be);
            }
            float l, h;
            UNPACK2(l, h, t);  float tf  = l + h;
            UNPACK2(l, h, s1); float s1f = l + h;
            UNPACK2(l, h, s2); float s2f = l + h;
            #pragma unroll
            for (int off = 16; off; off >>= 1) {
                tf  += __shfl_down_sync(FULL, tf,  off);
                s1f += __shfl_down_sync(FULL, s1f, off);
                s2f += __shfl_down_sync(FULL, s2f, off);
            }
            if (lane == 0) {
                float an = __ldg(&mu[i]) / tf;
                g_a[nxt][i] = an;
                double dan = (double)an;
                double dao = (double)__ldcg(&g_a[cur][i]);
                double dS1 = dan * dan * (double)s1f;
                double d = (it == 0)
                    ? dS1
                    : dS1 - 2.0 * dan * dao * (double)s2f + sDS1[warp];
                sDS1[warp] = dS1;
                sRow[warp] = d;
            }
        }
        __syncthreads();
        if (tid == 0) {
            double s = 0.0;
            #pragma unroll
            for (int q = 0; q < NWS; ++q) s += sRow[q];
            g_bdisp[blk] = s;
        }
        fpar = nxt;
        gbar(base + (++gen) * NB);
    }

    if (blk == 0 && tid == 0) g_final = fpar;
}

// ===================== Kernel 3: epilogue + last-block cost reduce ========
__global__ void __launch_bounds__(NTS, 1)
epi_kernel(float* __restrict__ out) {
    __shared__ float  sA[Mm];
    __shared__ float  sB[Mm];
    __shared__ double sRow[NWS];
    __shared__ int    sLast;

    const int tid = threadIdx.x, blk = blockIdx.x;
    const int warp = tid >> 5, lane = tid & 31;
    const unsigned FULL = 0xffffffffu;
    const int fpar = __ldcg(&g_final);

    float* Pout = out + 1;
    float* Cmat = out + 1 + (size_t)Nn * Mm;

    for (int i = tid; i < Mm; i += NTS) sA[i] = __ldcg(&g_b[fpar][i]);
    __syncthreads();
    for (int m = tid; m < Mm - 3; m += NTS) sB[m] = sA[m + 3];
    __syncthreads();
    const float4* Bsh4 = (const float4*)sB;

    {
        const int i = blk * 32 + warp;           // 1 row per warp
        const float ai = __ldcg(&g_a[fpar][i]);
        const float*  Kr = g_K + (size_t)i * Mm;
        const float4* K4 = (const float4*)Kr;
        float* Pr = Pout + (size_t)i * Mm;
        float* Cr = Cmat + (size_t)i * Mm;
        float csum = 0.f;

        if (lane < 3) {                  // head j = 0,1,2
            float k = Kr[lane];
            float p = ai * k * sA[lane];
            float c = -69.31471805599453f * __log2f(k);
            __stcs(Pr + lane, p);
            __stcs(Cr + lane, c);
            csum = fmaf(p, c, csum);
        }

        float4 curr = K4[lane];
        for (int s = 0; s < 32; s++) {
            const int q = lane + 32 * s;
            const int nidx = (s < 31) ? (lane + 32 * (s + 1)) : lane;
            float4 newq = K4[nidx];
            float nx = __shfl_down_sync(FULL, curr.x, 1);
            float ny = __shfl_down_sync(FULL, curr.y, 1);
            float nz = __shfl_down_sync(FULL, curr.z, 1);
            float bx = __shfl_sync(FULL, newq.x, 0);
            float by = __shfl_sync(FULL, newq.y, 0);
            float bz = __shfl_sync(FULL, newq.z, 0);
            if (lane == 31) { nx = bx; ny = by; nz = bz; }

            if (q <= 1022) {
                const int jst = 4 * q + 3;
                float k0 = curr.w, k1 = nx, k2 = ny, k3 = nz;
                float4 bq = Bsh4[q];
                float p0 = ai * k0 * bq.x, p1 = ai * k1 * bq.y;
                float p2 = ai * k2 * bq.z, p3 = ai * k3 * bq.w;
                float c0 = -69.31471805599453f * __log2f(k0);
                float c1 = -69.31471805599453f * __log2f(k1);
                float c2 = -69.31471805599453f * __log2f(k2);
                float c3 = -69.31471805599453f * __log2f(k3);
                float4 pq; pq.x = p0; pq.y = p1; pq.z = p2; pq.w = p3;
                float4 cq; cq.x = c0; cq.y = c1; cq.z = c2; cq.w = c3;
                __stcs((float4*)(Pr + jst), pq);
                __stcs((float4*)(Cr + jst), cq);
                csum = fmaf(p0, c0, csum); csum = fmaf(p1, c1, csum);
                csum = fmaf(p2, c2, csum); csum = fmaf(p3, c3, csum);
            }
            if (s == 31 && lane == 31) {  // tail j = 4095
                float k = curr.w;
                float p = ai * k * sA[4095];
                float c = -69.31471805599453f * __log2f(k);
                __stcs(Pr + 4095, p);
                __stcs(Cr + 4095, c);
                csum = fmaf(p, c, csum);
            }
            curr = newq;
        }

        #pragma unroll
        for (int off = 16; off; off >>= 1)
            csum += __shfl_down_sync(FULL, csum, off);
        if (lane == 0) sRow[warp] = (double)csum;
    }
    __syncthreads();
    if (tid == 0) {
        double s = 0.0;
        #pragma unroll
        for (int q = 0; q < NWS; ++q) s += sRow[q];
        g_bcost[blk] = s;
        __threadfence();
        unsigned old;
        asm volatile("atom.global.add.u32 %0, [%1], 1;"
                     : "=r"(old) : "l"(&g_epi_ticket) : "memory");
        sLast = ((old + 1) % NB == 0);
    }
    __syncthreads();
    if (sLast) {
        __threadfence();
        if (warp == 0) {
            double sc = __ldcg(&g_bcost[lane])      + __ldcg(&g_bcost[lane + 32])
                      + __ldcg(&g_bcost[lane + 64]) + __ldcg(&g_bcost[lane + 96]);
            #pragma unroll
            for (int off = 16; off; off >>= 1)
                sc += __shfl_down_sync(FULL, sc, off);
            if (lane == 0) out[0] = (float)sc;
        }
    }
}

// ---------------- launch ----------------
extern "C" void kernel_launch(void* const* d_in, const int* in_sizes, int n_in,
                              void* d_out, int out_size) {
    const float* x  = (const float*)d_in[0];
    const float* y  = (const float*)d_in[1];
    const float* mu = (const float*)d_in[2];
    const float* nu = (const float*)d_in[3];
    float* out = (float*)d_out;

    const int ck_smem = (256 * S2 + 256) * (int)sizeof(float);
    cudaFuncSetAttribute(ck_kernel, cudaFuncAttributeMaxDynamicSharedMemorySize, ck_smem);

    ck_kernel<<<NB, NT, ck_smem>>>(x, y);
    sink_kernel<<<NB, NTS>>>(mu, nu);
    epi_kernel<<<NB, NTS>>>(out);
}